// round 1
// baseline (speedup 1.0000x reference)
#include <cuda_runtime.h>
#include <math.h>

#define BB 8
#define TT 2048
#define CC 768
#define NHEAD 12
#define HS 64
#define NSEG 255
#define BH (BB*NHEAD)   // 96
#define QKVROW (3*CC)   // 2304

// -------- scratch (device globals; allocation-free contract) --------
__device__ float g_qkv [(size_t)BB*TT*QKVROW];     // (b*T+t, 2304): q|k|v0
__device__ float g_v   [(size_t)BH*TT*HS];         // v, then vcum in-place
__device__ float g_kcum[(size_t)BH*TT*HS];
__device__ float g_Kseg[(size_t)BH*NSEG*HS];
__device__ float g_Vseg[(size_t)BH*NSEG*HS];
__device__ float g_att [(size_t)BB*TT*CC];         // (b*T+t, h*64+d)
__device__ int   g_l[NSEG];
__device__ int   g_r[NSEG];

// -------- kernel 1: segment table --------
__global__ void seg_init_kernel() {
    int s = threadIdx.x;
    if (s >= NSEG) return;
    int off = 0, cnt = 128, lv = 0;
    while (s >= off + cnt) { off += cnt; cnt >>= 1; lv++; }
    int i = s - off;
    int L = 16 << lv;
    g_l[s] = i * L;
    g_r[s] = (i + 1) * L - 1;
}

// -------- kernel 2/7: C(M,N) = A(M,K) @ B(N,K)^T, fp32 tiled --------
__global__ __launch_bounds__(256) void sgemm_tn(
    float* __restrict__ Cc, const float* __restrict__ A,
    const float* __restrict__ Bm, int M, int N, int K)
{
    constexpr int BK = 8;
    __shared__ float As[BK][128];
    __shared__ float Bs[BK][128];
    const int tid = threadIdx.x;
    const int tx = tid & 15, ty = tid >> 4;
    const int lrow = tid >> 1;
    const int lcol = (tid & 1) << 2;

    const float* Ab = A + (size_t)blockIdx.y * 128 * K + (size_t)lrow * K + lcol;
    const float* Bb = Bm + (size_t)blockIdx.x * 128 * K + (size_t)lrow * K + lcol;

    float acc[8][8];
    #pragma unroll
    for (int i = 0; i < 8; i++)
        #pragma unroll
        for (int j = 0; j < 8; j++) acc[i][j] = 0.f;

    for (int k0 = 0; k0 < K; k0 += BK) {
        float4 a = *(const float4*)(Ab + k0);
        float4 b = *(const float4*)(Bb + k0);
        As[lcol+0][lrow] = a.x; As[lcol+1][lrow] = a.y;
        As[lcol+2][lrow] = a.z; As[lcol+3][lrow] = a.w;
        Bs[lcol+0][lrow] = b.x; Bs[lcol+1][lrow] = b.y;
        Bs[lcol+2][lrow] = b.z; Bs[lcol+3][lrow] = b.w;
        __syncthreads();
        #pragma unroll
        for (int kk = 0; kk < BK; kk++) {
            float4 a0 = *(const float4*)&As[kk][ty*8];
            float4 a1 = *(const float4*)&As[kk][ty*8+4];
            float4 b0 = *(const float4*)&Bs[kk][tx*8];
            float4 b1 = *(const float4*)&Bs[kk][tx*8+4];
            float ar[8] = {a0.x,a0.y,a0.z,a0.w,a1.x,a1.y,a1.z,a1.w};
            float br[8] = {b0.x,b0.y,b0.z,b0.w,b1.x,b1.y,b1.z,b1.w};
            #pragma unroll
            for (int i = 0; i < 8; i++)
                #pragma unroll
                for (int j = 0; j < 8; j++)
                    acc[i][j] = fmaf(ar[i], br[j], acc[i][j]);
        }
        __syncthreads();
    }
    float* Cp = Cc + (size_t)(blockIdx.y*128 + ty*8) * N + blockIdx.x*128 + tx*8;
    #pragma unroll
    for (int i = 0; i < 8; i++) {
        *(float4*)(Cp + (size_t)i*N)     = make_float4(acc[i][0],acc[i][1],acc[i][2],acc[i][3]);
        *(float4*)(Cp + (size_t)i*N + 4) = make_float4(acc[i][4],acc[i][5],acc[i][6],acc[i][7]);
    }
}

// -------- kernel 3: v[b,h,t,e] = sum_ij k_i v0_j Wv[e, i*64+j] + bv[e] --------
__global__ __launch_bounds__(128) void v_einsum_kernel(
    float* __restrict__ gv, const float* __restrict__ qkv,
    const float* __restrict__ Wv, const float* __restrict__ bv)
{
    __shared__ float4 As[1024];   // one A_e: 64x64 f32 as float4[16] per row
    const int bh = blockIdx.x;
    const int b = bh / NHEAD, h = bh % NHEAD;
    const int t = blockIdx.y * 128 + threadIdx.x;

    const float* rowp = qkv + ((size_t)(b*TT + t)) * QKVROW + h * HS;
    float  krf[64];
    float4 vr[16];
    #pragma unroll
    for (int j = 0; j < 16; j++) {
        float4 kk = *(const float4*)(rowp + CC + j*4);       // k
        krf[j*4+0] = kk.x; krf[j*4+1] = kk.y; krf[j*4+2] = kk.z; krf[j*4+3] = kk.w;
        vr[j] = *(const float4*)(rowp + 2*CC + j*4);         // v0
    }

    float* outp = gv + ((size_t)bh * TT + t) * HS;
    for (int e = 0; e < 64; e++) {
        __syncthreads();   // previous iteration's reads done
        const float4* we = (const float4*)(Wv + (size_t)e * 4096);
        #pragma unroll
        for (int idx = 0; idx < 8; idx++)
            As[threadIdx.x + idx*128] = we[threadIdx.x + idx*128];
        __syncthreads();

        float acc = 0.f;
        #pragma unroll
        for (int i = 0; i < 64; i++) {
            const float4* arow = &As[i*16];
            float u = 0.f;
            #pragma unroll
            for (int j = 0; j < 16; j++) {
                float4 a = arow[j];
                u = fmaf(a.x, vr[j].x, u);
                u = fmaf(a.y, vr[j].y, u);
                u = fmaf(a.z, vr[j].z, u);
                u = fmaf(a.w, vr[j].w, u);
            }
            acc = fmaf(krf[i], u, acc);
        }
        outp[e] = acc + bv[e];
    }
}

// -------- kernel 4: cumsum over t (k: qkv->g_kcum, v: in-place) --------
__global__ void cumsum_kernel(float* __restrict__ kcum, float* __restrict__ v,
                              const float* __restrict__ qkv)
{
    const int bh = blockIdx.x;
    const int b = bh / NHEAD, h = bh % NHEAD;
    const int tid = threadIdx.x;
    if (tid < HS) {
        const int d = tid;
        const float* src = qkv + (size_t)(b*TT) * QKVROW + CC + h*HS + d;
        float* dst = kcum + (size_t)bh * TT * HS + d;
        float s = 0.f;
        #pragma unroll 8
        for (int t = 0; t < TT; t++) { s += src[(size_t)t * QKVROW]; dst[t*HS] = s; }
    } else if (tid < 2*HS) {
        const int d = tid - HS;
        float* p = v + (size_t)bh * TT * HS + d;
        float s = 0.f;
        #pragma unroll 8
        for (int t = 0; t < TT; t++) { s += p[t*HS]; p[t*HS] = s; }
    }
}

// -------- kernel 5: segment K/V from cumsums --------
__global__ void seg_gather_kernel(float* __restrict__ Kseg, float* __restrict__ Vseg,
                                  const float* __restrict__ kcum, const float* __restrict__ vcum)
{
    const int bh = blockIdx.x;
    const float* kc = kcum + (size_t)bh * TT * HS;
    const float* vc = vcum + (size_t)bh * TT * HS;
    for (int idx = threadIdx.x; idx < NSEG * HS; idx += blockDim.x) {
        int s = idx >> 6, d = idx & 63;
        int l = g_l[s], r = g_r[s];
        float kv = kc[r*HS + d], vv = vc[r*HS + d];
        if (l >= 1) { kv -= kc[(l-1)*HS + d]; vv -= vc[(l-1)*HS + d]; }
        Kseg[(size_t)bh * NSEG * HS + idx] = kv;
        Vseg[(size_t)bh * NSEG * HS + idx] = vv;
    }
}

// -------- kernel 6: attention (one token per thread, online softmax) --------
__global__ __launch_bounds__(128) void attn_kernel(
    float* __restrict__ out, const float* __restrict__ qkv,
    const float* __restrict__ kcum, const float* __restrict__ vcum,
    const float* __restrict__ Kseg, const float* __restrict__ Vseg)
{
    extern __shared__ float sm[];
    float* Ks = sm;                 // NSEG*HS
    float* Vs = sm + NSEG * HS;
    const int bh = blockIdx.x;
    const int b = bh / NHEAD, h = bh % NHEAD;
    const int t = blockIdx.y * 128 + threadIdx.x;

    {   // stage segment K/V to smem
        const float4* Kg = (const float4*)(Kseg + (size_t)bh * NSEG * HS);
        const float4* Vg = (const float4*)(Vseg + (size_t)bh * NSEG * HS);
        float4* Ks4 = (float4*)Ks; float4* Vs4 = (float4*)Vs;
        for (int idx = threadIdx.x; idx < NSEG*HS/4; idx += 128) {
            Ks4[idx] = Kg[idx];
            Vs4[idx] = Vg[idx];
        }
    }
    __syncthreads();

    float4 q4[16];
    const float* qp = qkv + ((size_t)(b*TT + t)) * QKVROW + h * HS;
    #pragma unroll
    for (int j = 0; j < 16; j++) q4[j] = *(const float4*)(qp + j*4);

    float mmax = -INFINITY, lsum = 0.f;
    float4 acc4[16];
    #pragma unroll
    for (int j = 0; j < 16; j++) acc4[j] = make_float4(0.f,0.f,0.f,0.f);

    const float scale = 0.125f;   // 1/sqrt(64)
    int off = 0;
    #pragma unroll 1
    for (int lv = 0; lv < 8; lv++) {
        const int nvalid = (t + 1) >> (4 + lv);
        #pragma unroll 1
        for (int i = 0; i < nvalid; i++) {
            const int s = off + i;
            const float4* kp = (const float4*)(Ks + s*HS);
            float lg = 0.f;
            #pragma unroll
            for (int j = 0; j < 16; j++) {
                float4 kk = kp[j];
                lg = fmaf(kk.x, q4[j].x, lg); lg = fmaf(kk.y, q4[j].y, lg);
                lg = fmaf(kk.z, q4[j].z, lg); lg = fmaf(kk.w, q4[j].w, lg);
            }
            lg *= scale;
            if (lg > mmax) {
                float c = __expf(mmax - lg);
                lsum *= c;
                #pragma unroll
                for (int j = 0; j < 16; j++) {
                    acc4[j].x *= c; acc4[j].y *= c; acc4[j].z *= c; acc4[j].w *= c;
                }
                mmax = lg;
            }
            float p = __expf(lg - mmax);
            lsum += p;
            const float4* vp = (const float4*)(Vs + s*HS);
            #pragma unroll
            for (int j = 0; j < 16; j++) {
                float4 vv = vp[j];
                acc4[j].x = fmaf(p, vv.x, acc4[j].x);
                acc4[j].y = fmaf(p, vv.y, acc4[j].y);
                acc4[j].z = fmaf(p, vv.z, acc4[j].z);
                acc4[j].w = fmaf(p, vv.w, acc4[j].w);
            }
        }
        off += 128 >> lv;
    }

    // tail: [l_tail, t], l_tail = t & ~15
    const int lt = t & ~15;
    const float4* kc4 = (const float4*)(kcum + (size_t)bh * TT * HS);
    const float4* vc4 = (const float4*)(vcum + (size_t)bh * TT * HS);
    float lg = 0.f;
    #pragma unroll
    for (int j = 0; j < 16; j++) {
        float4 kt = kc4[t*16 + j];
        if (lt >= 1) {
            float4 kl = kc4[(lt-1)*16 + j];
            kt.x -= kl.x; kt.y -= kl.y; kt.z -= kl.z; kt.w -= kl.w;
        }
        lg = fmaf(kt.x, q4[j].x, lg); lg = fmaf(kt.y, q4[j].y, lg);
        lg = fmaf(kt.z, q4[j].z, lg); lg = fmaf(kt.w, q4[j].w, lg);
    }
    lg *= scale;
    if (lg > mmax) {
        float c = __expf(mmax - lg);
        lsum *= c;
        #pragma unroll
        for (int j = 0; j < 16; j++) {
            acc4[j].x *= c; acc4[j].y *= c; acc4[j].z *= c; acc4[j].w *= c;
        }
        mmax = lg;
    }
    {
        float p = __expf(lg - mmax);
        lsum += p;
        #pragma unroll
        for (int j = 0; j < 16; j++) {
            float4 vt = vc4[t*16 + j];
            if (lt >= 1) {
                float4 vl = vc4[(lt-1)*16 + j];
                vt.x -= vl.x; vt.y -= vl.y; vt.z -= vl.z; vt.w -= vl.w;
            }
            acc4[j].x = fmaf(p, vt.x, acc4[j].x);
            acc4[j].y = fmaf(p, vt.y, acc4[j].y);
            acc4[j].z = fmaf(p, vt.z, acc4[j].z);
            acc4[j].w = fmaf(p, vt.w, acc4[j].w);
        }
    }

    const float inv = 1.0f / lsum;
    float* op = out + ((size_t)(b*TT + t)) * CC + h * HS;
    #pragma unroll
    for (int j = 0; j < 16; j++) {
        *(float4*)(op + j*4) = make_float4(acc4[j].x*inv, acc4[j].y*inv,
                                           acc4[j].z*inv, acc4[j].w*inv);
    }
}

// -------- launch --------
extern "C" void kernel_launch(void* const* d_in, const int* in_sizes, int n_in,
                              void* d_out, int out_size)
{
    const float* x     = (const float*)d_in[0];
    const float* Wqkv  = (const float*)d_in[1];
    const float* Wproj = (const float*)d_in[2];
    const float* Wv    = (const float*)d_in[3];
    const float* bv    = (const float*)d_in[4];
    float* out = (float*)d_out;

    float *qkv, *v, *kcum, *Kseg, *Vseg, *att;
    cudaGetSymbolAddress((void**)&qkv,  g_qkv);
    cudaGetSymbolAddress((void**)&v,    g_v);
    cudaGetSymbolAddress((void**)&kcum, g_kcum);
    cudaGetSymbolAddress((void**)&Kseg, g_Kseg);
    cudaGetSymbolAddress((void**)&Vseg, g_Vseg);
    cudaGetSymbolAddress((void**)&att,  g_att);

    const int attn_smem = 2 * NSEG * HS * (int)sizeof(float);   // 130560
    cudaFuncSetAttribute(attn_kernel, cudaFuncAttributeMaxDynamicSharedMemorySize, attn_smem);

    seg_init_kernel<<<1, 256>>>();

    // qkv = x @ Wqkv^T : M=16384, N=2304, K=768
    sgemm_tn<<<dim3(QKVROW/128, (BB*TT)/128), 256>>>(qkv, x, Wqkv, BB*TT, QKVROW, CC);

    // v bilinear map
    v_einsum_kernel<<<dim3(BH, TT/128), 128>>>(v, qkv, Wv, bv);

    // cumsums (k -> g_kcum, v in-place -> vcum)
    cumsum_kernel<<<BH, 128>>>(kcum, v, qkv);

    // segment K/V
    seg_gather_kernel<<<BH, 256>>>(Kseg, Vseg, kcum, v);

    // attention
    attn_kernel<<<dim3(BH, TT/128), 128, attn_smem>>>(att, qkv, kcum, v, Kseg, Vseg);

    // final projection: out = att @ Wproj^T : M=16384, N=768, K=768
    sgemm_tn<<<dim3(CC/128, (BB*TT)/128), 256>>>(out, att, Wproj, BB*TT, CC, CC);
}

// round 5
// speedup vs baseline: 1.5910x; 1.5910x over previous
#include <cuda_runtime.h>
#include <math.h>
#include <cstdint>

#define BB 8
#define TT 2048
#define CC 768
#define NHEAD 12
#define HS 64
#define NSEG 255
#define BH (BB*NHEAD)   // 96
#define QKVROW (3*CC)   // 2304

// ---------------- scratch ----------------
__device__ float g_qkv [(size_t)BB*TT*QKVROW];
__device__ float g_v   [(size_t)BH*TT*HS];
__device__ float g_kcum[(size_t)BH*TT*HS];
__device__ float g_Kseg[(size_t)BH*NSEG*HS];
__device__ float g_Vseg[(size_t)BH*NSEG*HS];
__device__ float g_att [(size_t)BB*TT*CC];
__device__ float g_ctot[BH][2][8][HS];
__device__ int   g_l[NSEG];
__device__ int   g_r[NSEG];

// ---------------- helpers ----------------
__device__ __forceinline__ uint32_t smem_u32(const void* p) {
    uint32_t a;
    asm("{ .reg .u64 t; cvta.to.shared.u64 t, %1; cvt.u32.u64 %0, t; }" : "=r"(a) : "l"(p));
    return a;
}
__device__ __forceinline__ void cpa16(uint32_t d, const void* s) {
    asm volatile("cp.async.cg.shared.global [%0], [%1], 16;" :: "r"(d), "l"(s));
}
__device__ __forceinline__ void cpa_commit() { asm volatile("cp.async.commit_group;"); }
template<int N> __device__ __forceinline__ void cpa_wait() {
    asm volatile("cp.async.wait_group %0;" :: "n"(N));
}

// m16n8k8 tf32 mma, D += A*B
__device__ __forceinline__ void mma8(float* d, const uint32_t* a, const uint32_t* b) {
    asm volatile(
        "mma.sync.aligned.m16n8k8.row.col.f32.tf32.tf32.f32 "
        "{%0,%1,%2,%3}, {%4,%5,%6,%7}, {%8,%9}, {%0,%1,%2,%3};"
        : "+f"(d[0]), "+f"(d[1]), "+f"(d[2]), "+f"(d[3])
        : "r"(a[0]), "r"(a[1]), "r"(a[2]), "r"(a[3]), "r"(b[0]), "r"(b[1]));
}

// split x into tf32 hi + tf32 lo (3xTF32 error compensation)
__device__ __forceinline__ void split2(float x, uint32_t& hb, uint32_t& lb) {
    uint32_t h;
    asm("cvt.rna.tf32.f32 %0, %1;" : "=r"(h) : "f"(x));
    float r = x - __uint_as_float(h);
    asm("cvt.rna.tf32.f32 %0, %1;" : "=r"(lb) : "f"(r));
    hb = h;
}

// ---------------- kernel: segment table ----------------
__global__ void seg_init_kernel() {
    int s = threadIdx.x;
    if (s >= NSEG) return;
    int off = 0, cnt = 128, lv = 0;
    while (s >= off + cnt) { off += cnt; cnt >>= 1; lv++; }
    int i = s - off;
    int L = 16 << lv;
    g_l[s] = i * L;
    g_r[s] = (i + 1) * L - 1;
}

// ---------------- 3xtf32 mma GEMM: C(M,N) = A(M,K) @ B(N,K)^T ----------------
// grid (N/128, M/128), 256 threads. BK=32, 3 stages, pad 36.
#define GPAD 36
#define GSTAGEF (128*GPAD*2)       // floats per stage (A then B)
__global__ __launch_bounds__(256) void mma_gemm_tn(
    float* __restrict__ C, const float* __restrict__ A, const float* __restrict__ B,
    int N, int K)
{
    extern __shared__ float sm[];
    const int tid = threadIdx.x;
    const int lane = tid & 31;
    const int wid = tid >> 5;
    const int wm = wid & 1;          // 0..1 (64 rows each)
    const int wn = wid >> 1;         // 0..3 (32 cols each)

    const int m0 = blockIdx.y << 7;
    const int n0 = blockIdx.x << 7;
    const float* At = A + (size_t)m0 * K;
    const float* Bt = B + (size_t)n0 * K;
    const int NC = K >> 5;

    const uint32_t smb = smem_u32(sm);

    auto load_stage = [&](int chunk, int stg) {
        const uint32_t sa = smb + stg * GSTAGEF * 4;
        const uint32_t sb = sa + 128 * GPAD * 4;
        const int k0 = chunk << 5;
        #pragma unroll
        for (int p = 0; p < 4; p++) {
            int idx = tid + (p << 8);       // 0..1023
            int row = idx >> 3;
            int seg = idx & 7;              // 4-float segment
            uint32_t off = (uint32_t)(row * GPAD + seg * 4) * 4;
            cpa16(sa + off, At + (size_t)row * K + k0 + seg * 4);
            cpa16(sb + off, Bt + (size_t)row * K + k0 + seg * 4);
        }
    };

    float acc[4][4][4];
    #pragma unroll
    for (int mt = 0; mt < 4; mt++)
        #pragma unroll
        for (int nt = 0; nt < 4; nt++)
            #pragma unroll
            for (int q = 0; q < 4; q++) acc[mt][nt][q] = 0.f;

    load_stage(0, 0); cpa_commit();
    load_stage(1, 1); cpa_commit();

    for (int c = 0; c < NC; c++) {
        if (c + 2 < NC) load_stage(c + 2, (c + 2) % 3);
        cpa_commit();
        cpa_wait<2>();
        __syncthreads();

        const float* as = sm + (c % 3) * GSTAGEF;
        const float* bs = as + 128 * GPAD;
        #pragma unroll
        for (int ks = 0; ks < 4; ks++) {
            uint32_t ab[4][4], al[4][4], bb[4][2], bl[4][2];
            const int c0 = ks * 8 + (lane & 3);
            #pragma unroll
            for (int mt = 0; mt < 4; mt++) {
                const int r0 = wm * 64 + mt * 16 + (lane >> 2);
                split2(as[r0 * GPAD + c0],           ab[mt][0], al[mt][0]);
                split2(as[(r0 + 8) * GPAD + c0],     ab[mt][1], al[mt][1]);
                split2(as[r0 * GPAD + c0 + 4],       ab[mt][2], al[mt][2]);
                split2(as[(r0 + 8) * GPAD + c0 + 4], ab[mt][3], al[mt][3]);
            }
            #pragma unroll
            for (int nt = 0; nt < 4; nt++) {
                const int n = wn * 32 + nt * 8 + (lane >> 2);
                split2(bs[n * GPAD + c0],     bb[nt][0], bl[nt][0]);
                split2(bs[n * GPAD + c0 + 4], bb[nt][1], bl[nt][1]);
            }
            #pragma unroll
            for (int mt = 0; mt < 4; mt++)
                #pragma unroll
                for (int nt = 0; nt < 4; nt++) {
                    mma8(acc[mt][nt], ab[mt], bl[nt]);
                    mma8(acc[mt][nt], al[mt], bb[nt]);
                    mma8(acc[mt][nt], ab[mt], bb[nt]);
                }
        }
        __syncthreads();
    }

    // epilogue
    #pragma unroll
    for (int mt = 0; mt < 4; mt++) {
        const int row = m0 + wm * 64 + mt * 16 + (lane >> 2);
        #pragma unroll
        for (int nt = 0; nt < 4; nt++) {
            const int col = n0 + wn * 32 + nt * 8 + ((lane & 3) << 1);
            *(float2*)&C[(size_t)row * N + col]       = make_float2(acc[mt][nt][0], acc[mt][nt][1]);
            *(float2*)&C[(size_t)(row + 8) * N + col] = make_float2(acc[mt][nt][2], acc[mt][nt][3]);
        }
    }
}

// ---------------- fused v bilinear as 3xtf32 mma GEMM ----------------
// v(128 tokens, 64) += Z(128, 4096) @ Wv(64, 4096)^T, Z built on the fly.
#define VPAD 36
__global__ __launch_bounds__(256) void v_mma_kernel(
    float* __restrict__ gv, const float* __restrict__ qkv,
    const float* __restrict__ Wv, const float* __restrict__ bv)
{
    extern __shared__ float sm[];
    float* ksm = sm;                         // 128*64
    float* zsm = sm + 128 * 64;              // 128*VPAD
    float* wsm = zsm + 128 * VPAD;           // 2 * 64*VPAD
    const uint32_t wsmb = smem_u32(wsm);

    const int tid = threadIdx.x;
    const int lane = tid & 31;
    const int wid = tid >> 5;
    const int bh = blockIdx.x >> 4;
    const int t0 = (blockIdx.x & 15) << 7;
    const int b = bh / NHEAD, h = bh % NHEAD;

    const float* qbase = qkv + (size_t)(b * TT + t0) * QKVROW + h * HS;

    // stage k into smem (128 x 64)
    #pragma unroll
    for (int p = 0; p < 8; p++) {
        int idx = tid + (p << 8);           // 0..2047 float4s
        int row = idx >> 4;
        int c4 = idx & 15;
        float4 kk = *(const float4*)(qbase + (size_t)row * QKVROW + CC + c4 * 4);
        *(float4*)&ksm[row * 64 + c4 * 4] = kk;
    }

    // v0 into registers: rows {tr2 + 8m}, col jj (two 32-halves)
    const int jj = tid & 31;
    const int tr2 = tid >> 5;                // 0..7 == warp id
    float v0a[16], v0b[16];
    #pragma unroll
    for (int m = 0; m < 16; m++) {
        const float* rp = qbase + (size_t)(tr2 + 8 * m) * QKVROW + 2 * CC;
        v0a[m] = rp[jj];
        v0b[m] = rp[32 + jj];
    }

    auto loadW = [&](int kc, int buf) {
        const uint32_t dst = wsmb + (uint32_t)buf * 64 * VPAD * 4;
        #pragma unroll
        for (int p = 0; p < 2; p++) {
            int idx = tid + (p << 8);       // 0..511
            int row = idx >> 3;             // e 0..63
            int seg = idx & 7;
            cpa16(dst + (uint32_t)(row * VPAD + seg * 4) * 4,
                  Wv + (size_t)row * 4096 + kc * 32 + seg * 4);
        }
    };

    loadW(0, 0); cpa_commit();
    loadW(1, 1); cpa_commit();

    const int wm = wid >> 1;   // 0..3 (32 rows each)
    const int wn = wid & 1;    // 0..1 (32 cols each)
    float acc[2][4][4];
    #pragma unroll
    for (int mt = 0; mt < 2; mt++)
        #pragma unroll
        for (int nt = 0; nt < 4; nt++)
            #pragma unroll
            for (int q = 0; q < 4; q++) acc[mt][nt][q] = 0.f;

    __syncthreads();   // ksm visible

    for (int kc = 0; kc < 128; kc++) {
        cpa_wait<1>();
        __syncthreads();   // W[kc] visible; previous mma done with zsm

        // build Z slab: z[t][jj] = k[t][i] * v0[t][j0+jj]
        const int i = kc >> 1;
        const bool hi = kc & 1;
        #pragma unroll
        for (int m = 0; m < 16; m++) {
            const int row = tr2 + 8 * m;
            float kval = ksm[row * 64 + i];
            float vv = hi ? v0b[m] : v0a[m];
            zsm[row * VPAD + jj] = kval * vv;
        }
        __syncthreads();

        const float* ws = wsm + (kc & 1) * 64 * VPAD;
        #pragma unroll
        for (int ks = 0; ks < 4; ks++) {
            const int c0 = ks * 8 + (lane & 3);
            uint32_t ab[2][4], al[2][4], bb[4][2], bl[4][2];
            #pragma unroll
            for (int mt = 0; mt < 2; mt++) {
                const int r0 = wm * 32 + mt * 16 + (lane >> 2);
                split2(zsm[r0 * VPAD + c0],           ab[mt][0], al[mt][0]);
                split2(zsm[(r0 + 8) * VPAD + c0],     ab[mt][1], al[mt][1]);
                split2(zsm[r0 * VPAD + c0 + 4],       ab[mt][2], al[mt][2]);
                split2(zsm[(r0 + 8) * VPAD + c0 + 4], ab[mt][3], al[mt][3]);
            }
            #pragma unroll
            for (int nt = 0; nt < 4; nt++) {
                const int n = wn * 32 + nt * 8 + (lane >> 2);
                split2(ws[n * VPAD + c0],     bb[nt][0], bl[nt][0]);
                split2(ws[n * VPAD + c0 + 4], bb[nt][1], bl[nt][1]);
            }
            #pragma unroll
            for (int mt = 0; mt < 2; mt++)
                #pragma unroll
                for (int nt = 0; nt < 4; nt++) {
                    mma8(acc[mt][nt], ab[mt], bl[nt]);
                    mma8(acc[mt][nt], al[mt], bb[nt]);
                    mma8(acc[mt][nt], ab[mt], bb[nt]);
                }
        }
        __syncthreads();

        if (kc + 2 < 128) loadW(kc + 2, kc & 1);
        cpa_commit();
    }

    // epilogue: add bias, write g_v[bh][t0+row][e]
    #pragma unroll
    for (int mt = 0; mt < 2; mt++) {
        const int row = wm * 32 + mt * 16 + (lane >> 2);
        #pragma unroll
        for (int nt = 0; nt < 4; nt++) {
            const int e0 = wn * 32 + nt * 8 + ((lane & 3) << 1);
            const float b0 = __ldg(&bv[e0]), b1 = __ldg(&bv[e0 + 1]);
            float* o0 = gv + ((size_t)bh * TT + t0 + row) * HS + e0;
            float* o1 = gv + ((size_t)bh * TT + t0 + row + 8) * HS + e0;
            *(float2*)o0 = make_float2(acc[mt][nt][0] + b0, acc[mt][nt][1] + b1);
            *(float2*)o1 = make_float2(acc[mt][nt][2] + b0, acc[mt][nt][3] + b1);
        }
    }
}

// ---------------- cumsum: 2-phase chunked ----------------
__global__ void cumsum_part(float* __restrict__ kcum, float* __restrict__ v,
                            const float* __restrict__ qkv)
{
    const int bh = blockIdx.x, c = blockIdx.y;
    const int b = bh / NHEAD, h = bh % NHEAD;
    const int tid = threadIdx.x;
    const int t0 = c * 256;
    if (tid < HS) {
        const float* src = qkv + (size_t)(b*TT + t0) * QKVROW + CC + h*HS + tid;
        float* dst = kcum + ((size_t)bh*TT + t0) * HS + tid;
        float s = 0.f;
        #pragma unroll 8
        for (int t = 0; t < 256; t++) { s += src[(size_t)t * QKVROW]; dst[t*HS] = s; }
        g_ctot[bh][0][c][tid] = s;
    } else {
        const int d = tid - HS;
        float* p = v + ((size_t)bh*TT + t0) * HS + d;
        float s = 0.f;
        #pragma unroll 8
        for (int t = 0; t < 256; t++) { s += p[t*HS]; p[t*HS] = s; }
        g_ctot[bh][1][c][d] = s;
    }
}

__global__ void cumsum_fix(float* __restrict__ kcum, float* __restrict__ v)
{
    const int bh = blockIdx.x, c = blockIdx.y + 1;   // chunks 1..7
    const int tid = threadIdx.x;
    const int which = tid >> 6, d = tid & 63;
    float pre = 0.f;
    for (int j = 0; j < c; j++) pre += g_ctot[bh][which][j][d];
    float* p = (which ? v : kcum) + ((size_t)bh*TT + c*256) * HS + d;
    #pragma unroll 8
    for (int t = 0; t < 256; t++) p[t*HS] += pre;
}

// ---------------- segment K/V ----------------
__global__ void seg_gather_kernel(float* __restrict__ Kseg, float* __restrict__ Vseg,
                                  const float* __restrict__ kcum, const float* __restrict__ vcum)
{
    const int bh = blockIdx.x;
    const float* kc = kcum + (size_t)bh * TT * HS;
    const float* vc = vcum + (size_t)bh * TT * HS;
    for (int idx = threadIdx.x; idx < NSEG * HS; idx += blockDim.x) {
        int s = idx >> 6, d = idx & 63;
        int l = g_l[s], r = g_r[s];
        float kv = kc[r*HS + d], vv = vc[r*HS + d];
        if (l >= 1) { kv -= kc[(l-1)*HS + d]; vv -= vc[(l-1)*HS + d]; }
        Kseg[(size_t)bh * NSEG * HS + idx] = kv;
        Vseg[(size_t)bh * NSEG * HS + idx] = vv;
    }
}

// ---------------- attention (exact fp32, unchanged) ----------------
__global__ __launch_bounds__(128) void attn_kernel(
    float* __restrict__ out, const float* __restrict__ qkv,
    const float* __restrict__ kcum, const float* __restrict__ vcum,
    const float* __restrict__ Kseg, const float* __restrict__ Vseg)
{
    extern __shared__ float smf[];
    float* Ks = smf;
    float* Vs = smf + NSEG * HS;
    const int bh = blockIdx.x;
    const int b = bh / NHEAD, h = bh % NHEAD;
    const int t = blockIdx.y * 128 + threadIdx.x;

    {
        const float4* Kg = (const float4*)(Kseg + (size_t)bh * NSEG * HS);
        const float4* Vg = (const float4*)(Vseg + (size_t)bh * NSEG * HS);
        float4* Ks4 = (float4*)Ks; float4* Vs4 = (float4*)Vs;
        for (int idx = threadIdx.x; idx < NSEG*HS/4; idx += 128) {
            Ks4[idx] = Kg[idx];
            Vs4[idx] = Vg[idx];
        }
    }
    __syncthreads();

    float4 q4[16];
    const float* qp = qkv + ((size_t)(b*TT + t)) * QKVROW + h * HS;
    #pragma unroll
    for (int j = 0; j < 16; j++) q4[j] = *(const float4*)(qp + j*4);

    float mmax = -INFINITY, lsum = 0.f;
    float4 acc4[16];
    #pragma unroll
    for (int j = 0; j < 16; j++) acc4[j] = make_float4(0.f,0.f,0.f,0.f);

    const float scale = 0.125f;
    int off = 0;
    #pragma unroll 1
    for (int lv = 0; lv < 8; lv++) {
        const int nvalid = (t + 1) >> (4 + lv);
        #pragma unroll 1
        for (int i = 0; i < nvalid; i++) {
            const int s = off + i;
            const float4* kp = (const float4*)(Ks + s*HS);
            float lg = 0.f;
            #pragma unroll
            for (int j = 0; j < 16; j++) {
                float4 kk = kp[j];
                lg = fmaf(kk.x, q4[j].x, lg); lg = fmaf(kk.y, q4[j].y, lg);
                lg = fmaf(kk.z, q4[j].z, lg); lg = fmaf(kk.w, q4[j].w, lg);
            }
            lg *= scale;
            if (lg > mmax) {
                float cc = __expf(mmax - lg);
                lsum *= cc;
                #pragma unroll
                for (int j = 0; j < 16; j++) {
                    acc4[j].x *= cc; acc4[j].y *= cc; acc4[j].z *= cc; acc4[j].w *= cc;
                }
                mmax = lg;
            }
            float p = __expf(lg - mmax);
            lsum += p;
            const float4* vp = (const float4*)(Vs + s*HS);
            #pragma unroll
            for (int j = 0; j < 16; j++) {
                float4 vv = vp[j];
                acc4[j].x = fmaf(p, vv.x, acc4[j].x);
                acc4[j].y = fmaf(p, vv.y, acc4[j].y);
                acc4[j].z = fmaf(p, vv.z, acc4[j].z);
                acc4[j].w = fmaf(p, vv.w, acc4[j].w);
            }
        }
        off += 128 >> lv;
    }

    const int lt = t & ~15;
    const float4* kc4 = (const float4*)(kcum + (size_t)bh * TT * HS);
    const float4* vc4 = (const float4*)(vcum + (size_t)bh * TT * HS);
    float lg = 0.f;
    #pragma unroll
    for (int j = 0; j < 16; j++) {
        float4 kt = kc4[t*16 + j];
        if (lt >= 1) {
            float4 kl = kc4[(lt-1)*16 + j];
            kt.x -= kl.x; kt.y -= kl.y; kt.z -= kl.z; kt.w -= kl.w;
        }
        lg = fmaf(kt.x, q4[j].x, lg); lg = fmaf(kt.y, q4[j].y, lg);
        lg = fmaf(kt.z, q4[j].z, lg); lg = fmaf(kt.w, q4[j].w, lg);
    }
    lg *= scale;
    if (lg > mmax) {
        float cc = __expf(mmax - lg);
        lsum *= cc;
        #pragma unroll
        for (int j = 0; j < 16; j++) {
            acc4[j].x *= cc; acc4[j].y *= cc; acc4[j].z *= cc; acc4[j].w *= cc;
        }
        mmax = lg;
    }
    {
        float p = __expf(lg - mmax);
        lsum += p;
        #pragma unroll
        for (int j = 0; j < 16; j++) {
            float4 vt = vc4[t*16 + j];
            if (lt >= 1) {
                float4 vl = vc4[(lt-1)*16 + j];
                vt.x -= vl.x; vt.y -= vl.y; vt.z -= vl.z; vt.w -= vl.w;
            }
            acc4[j].x = fmaf(p, vt.x, acc4[j].x);
            acc4[j].y = fmaf(p, vt.y, acc4[j].y);
            acc4[j].z = fmaf(p, vt.z, acc4[j].z);
            acc4[j].w = fmaf(p, vt.w, acc4[j].w);
        }
    }

    const float inv = 1.0f / lsum;
    float* op = out + ((size_t)(b*TT + t)) * CC + h * HS;
    #pragma unroll
    for (int j = 0; j < 16; j++) {
        *(float4*)(op + j*4) = make_float4(acc4[j].x*inv, acc4[j].y*inv,
                                           acc4[j].z*inv, acc4[j].w*inv);
    }
}

// ---------------- launch ----------------
extern "C" void kernel_launch(void* const* d_in, const int* in_sizes, int n_in,
                              void* d_out, int out_size)
{
    const float* x     = (const float*)d_in[0];
    const float* Wqkv  = (const float*)d_in[1];
    const float* Wproj = (const float*)d_in[2];
    const float* Wv    = (const float*)d_in[3];
    const float* bv    = (const float*)d_in[4];
    float* out = (float*)d_out;

    float *qkv, *v, *kcum, *Kseg, *Vseg, *att;
    cudaGetSymbolAddress((void**)&qkv,  g_qkv);
    cudaGetSymbolAddress((void**)&v,    g_v);
    cudaGetSymbolAddress((void**)&kcum, g_kcum);
    cudaGetSymbolAddress((void**)&Kseg, g_Kseg);
    cudaGetSymbolAddress((void**)&Vseg, g_Vseg);
    cudaGetSymbolAddress((void**)&att,  g_att);

    const int gemm_smem = 3 * GSTAGEF * 4;                               // 110592
    cudaFuncSetAttribute(mma_gemm_tn, cudaFuncAttributeMaxDynamicSharedMemorySize, gemm_smem);
    const int v_smem = (128*64 + 128*VPAD + 2*64*VPAD) * 4;              // 69632
    cudaFuncSetAttribute(v_mma_kernel, cudaFuncAttributeMaxDynamicSharedMemorySize, v_smem);
    const int attn_smem = 2 * NSEG * HS * (int)sizeof(float);            // 130560
    cudaFuncSetAttribute(attn_kernel, cudaFuncAttributeMaxDynamicSharedMemorySize, attn_smem);

    seg_init_kernel<<<1, 256>>>();

    // qkv = x @ Wqkv^T : M=16384, N=2304, K=768
    mma_gemm_tn<<<dim3(QKVROW/128, (BB*TT)/128), 256, gemm_smem>>>(qkv, x, Wqkv, QKVROW, CC);

    // v bilinear via fused Z-GEMM
    v_mma_kernel<<<BH*TT/128, 256, v_smem>>>(v, qkv, Wv, bv);

    // cumsums, 2-phase
    cumsum_part<<<dim3(BH, 8), 128>>>(kcum, v, qkv);
    cumsum_fix<<<dim3(BH, 7), 128>>>(kcum, v);

    // segment K/V
    seg_gather_kernel<<<BH, 256>>>(Kseg, Vseg, kcum, v);

    // attention
    attn_kernel<<<dim3(BH, TT/128), 128, attn_smem>>>(att, qkv, kcum, v, Kseg, Vseg);

    // out = att @ Wproj^T : M=16384, N=768, K=768
    mma_gemm_tn<<<dim3(CC/128, (BB*TT)/128), 256, gemm_smem>>>(out, att, Wproj, CC, CC);
}

// round 6
// speedup vs baseline: 1.5913x; 1.0002x over previous
#include <cuda_runtime.h>
#include <math.h>
#include <cstdint>

#define BB 8
#define TT 2048
#define CC 768
#define NHEAD 12
#define HS 64
#define NSEG 255
#define BH (BB*NHEAD)   // 96
#define QKVROW (3*CC)   // 2304

// ---------------- scratch ----------------
__device__ float g_qkv [(size_t)BB*TT*QKVROW];
__device__ float g_v   [(size_t)BH*TT*HS];
__device__ float g_kcum[(size_t)BH*TT*HS];
__device__ float g_Kseg[(size_t)BH*NSEG*HS];
__device__ float g_Vseg[(size_t)BH*NSEG*HS];
__device__ float g_att [(size_t)BB*TT*CC];
__device__ float g_ctot[BH][2][8][HS];
__device__ int   g_l[NSEG];
__device__ int   g_r[NSEG];

// ---------------- helpers ----------------
__device__ __forceinline__ uint32_t smem_u32(const void* p) {
    uint32_t a;
    asm("{ .reg .u64 t; cvta.to.shared.u64 t, %1; cvt.u32.u64 %0, t; }" : "=r"(a) : "l"(p));
    return a;
}
__device__ __forceinline__ void cpa16(uint32_t d, const void* s) {
    asm volatile("cp.async.cg.shared.global [%0], [%1], 16;" :: "r"(d), "l"(s));
}
__device__ __forceinline__ void cpa_commit() { asm volatile("cp.async.commit_group;"); }
template<int N> __device__ __forceinline__ void cpa_wait() {
    asm volatile("cp.async.wait_group %0;" :: "n"(N));
}

// m16n8k8 tf32 mma, D += A*B
__device__ __forceinline__ void mma8(float* d, const uint32_t* a, const uint32_t* b) {
    asm volatile(
        "mma.sync.aligned.m16n8k8.row.col.f32.tf32.tf32.f32 "
        "{%0,%1,%2,%3}, {%4,%5,%6,%7}, {%8,%9}, {%0,%1,%2,%3};"
        : "+f"(d[0]), "+f"(d[1]), "+f"(d[2]), "+f"(d[3])
        : "r"(a[0]), "r"(a[1]), "r"(a[2]), "r"(a[3]), "r"(b[0]), "r"(b[1]));
}

// split x into tf32 hi + tf32 lo (3xTF32 error compensation)
__device__ __forceinline__ void split2(float x, uint32_t& hb, uint32_t& lb) {
    uint32_t h;
    asm("cvt.rna.tf32.f32 %0, %1;" : "=r"(h) : "f"(x));
    float r = x - __uint_as_float(h);
    asm("cvt.rna.tf32.f32 %0, %1;" : "=r"(lb) : "f"(r));
    hb = h;
}

// ---------------- kernel: segment table ----------------
__global__ void seg_init_kernel() {
    int s = threadIdx.x;
    if (s >= NSEG) return;
    int off = 0, cnt = 128, lv = 0;
    while (s >= off + cnt) { off += cnt; cnt >>= 1; lv++; }
    int i = s - off;
    int L = 16 << lv;
    g_l[s] = i * L;
    g_r[s] = (i + 1) * L - 1;
}

// ---------------- 3xtf32 mma GEMM: C(M,N) = A(M,K) @ B(N,K)^T ----------------
// grid (N/128, M/128), 256 threads. BK=32, 3 stages, pad 36.
#define GPAD 36
#define GSTAGEF (128*GPAD*2)       // floats per stage (A then B)
__global__ __launch_bounds__(256) void mma_gemm_tn(
    float* __restrict__ C, const float* __restrict__ A, const float* __restrict__ B,
    int N, int K)
{
    extern __shared__ float sm[];
    const int tid = threadIdx.x;
    const int lane = tid & 31;
    const int wid = tid >> 5;
    const int wm = wid & 1;          // 0..1 (64 rows each)
    const int wn = wid >> 1;         // 0..3 (32 cols each)

    const int m0 = blockIdx.y << 7;
    const int n0 = blockIdx.x << 7;
    const float* At = A + (size_t)m0 * K;
    const float* Bt = B + (size_t)n0 * K;
    const int NC = K >> 5;

    const uint32_t smb = smem_u32(sm);

    auto load_stage = [&](int chunk, int stg) {
        const uint32_t sa = smb + stg * GSTAGEF * 4;
        const uint32_t sb = sa + 128 * GPAD * 4;
        const int k0 = chunk << 5;
        #pragma unroll
        for (int p = 0; p < 4; p++) {
            int idx = tid + (p << 8);       // 0..1023
            int row = idx >> 3;
            int seg = idx & 7;              // 4-float segment
            uint32_t off = (uint32_t)(row * GPAD + seg * 4) * 4;
            cpa16(sa + off, At + (size_t)row * K + k0 + seg * 4);
            cpa16(sb + off, Bt + (size_t)row * K + k0 + seg * 4);
        }
    };

    float acc[4][4][4];
    #pragma unroll
    for (int mt = 0; mt < 4; mt++)
        #pragma unroll
        for (int nt = 0; nt < 4; nt++)
            #pragma unroll
            for (int q = 0; q < 4; q++) acc[mt][nt][q] = 0.f;

    load_stage(0, 0); cpa_commit();
    load_stage(1, 1); cpa_commit();

    for (int c = 0; c < NC; c++) {
        if (c + 2 < NC) load_stage(c + 2, (c + 2) % 3);
        cpa_commit();
        cpa_wait<2>();
        __syncthreads();

        const float* as = sm + (c % 3) * GSTAGEF;
        const float* bs = as + 128 * GPAD;
        #pragma unroll
        for (int ks = 0; ks < 4; ks++) {
            uint32_t ab[4][4], al[4][4], bb[4][2], bl[4][2];
            const int c0 = ks * 8 + (lane & 3);
            #pragma unroll
            for (int mt = 0; mt < 4; mt++) {
                const int r0 = wm * 64 + mt * 16 + (lane >> 2);
                split2(as[r0 * GPAD + c0],           ab[mt][0], al[mt][0]);
                split2(as[(r0 + 8) * GPAD + c0],     ab[mt][1], al[mt][1]);
                split2(as[r0 * GPAD + c0 + 4],       ab[mt][2], al[mt][2]);
                split2(as[(r0 + 8) * GPAD + c0 + 4], ab[mt][3], al[mt][3]);
            }
            #pragma unroll
            for (int nt = 0; nt < 4; nt++) {
                const int n = wn * 32 + nt * 8 + (lane >> 2);
                split2(bs[n * GPAD + c0],     bb[nt][0], bl[nt][0]);
                split2(bs[n * GPAD + c0 + 4], bb[nt][1], bl[nt][1]);
            }
            #pragma unroll
            for (int mt = 0; mt < 4; mt++)
                #pragma unroll
                for (int nt = 0; nt < 4; nt++) {
                    mma8(acc[mt][nt], ab[mt], bl[nt]);
                    mma8(acc[mt][nt], al[mt], bb[nt]);
                    mma8(acc[mt][nt], ab[mt], bb[nt]);
                }
        }
        __syncthreads();
    }

    // epilogue
    #pragma unroll
    for (int mt = 0; mt < 4; mt++) {
        const int row = m0 + wm * 64 + mt * 16 + (lane >> 2);
        #pragma unroll
        for (int nt = 0; nt < 4; nt++) {
            const int col = n0 + wn * 32 + nt * 8 + ((lane & 3) << 1);
            *(float2*)&C[(size_t)row * N + col]       = make_float2(acc[mt][nt][0], acc[mt][nt][1]);
            *(float2*)&C[(size_t)(row + 8) * N + col] = make_float2(acc[mt][nt][2], acc[mt][nt][3]);
        }
    }
}

// ---------------- fused v bilinear as 3xtf32 mma GEMM ----------------
// v(128 tokens, 64) += Z(128, 4096) @ Wv(64, 4096)^T, Z built on the fly.
#define VPAD 36
__global__ __launch_bounds__(256) void v_mma_kernel(
    float* __restrict__ gv, const float* __restrict__ qkv,
    const float* __restrict__ Wv, const float* __restrict__ bv)
{
    extern __shared__ float sm[];
    float* ksm = sm;                         // 128*64
    float* zsm = sm + 128 * 64;              // 128*VPAD
    float* wsm = zsm + 128 * VPAD;           // 2 * 64*VPAD
    const uint32_t wsmb = smem_u32(wsm);

    const int tid = threadIdx.x;
    const int lane = tid & 31;
    const int wid = tid >> 5;
    const int bh = blockIdx.x >> 4;
    const int t0 = (blockIdx.x & 15) << 7;
    const int b = bh / NHEAD, h = bh % NHEAD;

    const float* qbase = qkv + (size_t)(b * TT + t0) * QKVROW + h * HS;

    // stage k into smem (128 x 64)
    #pragma unroll
    for (int p = 0; p < 8; p++) {
        int idx = tid + (p << 8);           // 0..2047 float4s
        int row = idx >> 4;
        int c4 = idx & 15;
        float4 kk = *(const float4*)(qbase + (size_t)row * QKVROW + CC + c4 * 4);
        *(float4*)&ksm[row * 64 + c4 * 4] = kk;
    }

    // v0 into registers: rows {tr2 + 8m}, col jj (two 32-halves)
    const int jj = tid & 31;
    const int tr2 = tid >> 5;                // 0..7 == warp id
    float v0a[16], v0b[16];
    #pragma unroll
    for (int m = 0; m < 16; m++) {
        const float* rp = qbase + (size_t)(tr2 + 8 * m) * QKVROW + 2 * CC;
        v0a[m] = rp[jj];
        v0b[m] = rp[32 + jj];
    }

    auto loadW = [&](int kc, int buf) {
        const uint32_t dst = wsmb + (uint32_t)buf * 64 * VPAD * 4;
        #pragma unroll
        for (int p = 0; p < 2; p++) {
            int idx = tid + (p << 8);       // 0..511
            int row = idx >> 3;             // e 0..63
            int seg = idx & 7;
            cpa16(dst + (uint32_t)(row * VPAD + seg * 4) * 4,
                  Wv + (size_t)row * 4096 + kc * 32 + seg * 4);
        }
    };

    loadW(0, 0); cpa_commit();
    loadW(1, 1); cpa_commit();

    const int wm = wid >> 1;   // 0..3 (32 rows each)
    const int wn = wid & 1;    // 0..1 (32 cols each)
    float acc[2][4][4];
    #pragma unroll
    for (int mt = 0; mt < 2; mt++)
        #pragma unroll
        for (int nt = 0; nt < 4; nt++)
            #pragma unroll
            for (int q = 0; q < 4; q++) acc[mt][nt][q] = 0.f;

    __syncthreads();   // ksm visible

    for (int kc = 0; kc < 128; kc++) {
        cpa_wait<1>();
        __syncthreads();   // W[kc] visible; previous mma done with zsm

        // build Z slab: z[t][jj] = k[t][i] * v0[t][j0+jj]
        const int i = kc >> 1;
        const bool hi = kc & 1;
        #pragma unroll
        for (int m = 0; m < 16; m++) {
            const int row = tr2 + 8 * m;
            float kval = ksm[row * 64 + i];
            float vv = hi ? v0b[m] : v0a[m];
            zsm[row * VPAD + jj] = kval * vv;
        }
        __syncthreads();

        const float* ws = wsm + (kc & 1) * 64 * VPAD;
        #pragma unroll
        for (int ks = 0; ks < 4; ks++) {
            const int c0 = ks * 8 + (lane & 3);
            uint32_t ab[2][4], al[2][4], bb[4][2], bl[4][2];
            #pragma unroll
            for (int mt = 0; mt < 2; mt++) {
                const int r0 = wm * 32 + mt * 16 + (lane >> 2);
                split2(zsm[r0 * VPAD + c0],           ab[mt][0], al[mt][0]);
                split2(zsm[(r0 + 8) * VPAD + c0],     ab[mt][1], al[mt][1]);
                split2(zsm[r0 * VPAD + c0 + 4],       ab[mt][2], al[mt][2]);
                split2(zsm[(r0 + 8) * VPAD + c0 + 4], ab[mt][3], al[mt][3]);
            }
            #pragma unroll
            for (int nt = 0; nt < 4; nt++) {
                const int n = wn * 32 + nt * 8 + (lane >> 2);
                split2(ws[n * VPAD + c0],     bb[nt][0], bl[nt][0]);
                split2(ws[n * VPAD + c0 + 4], bb[nt][1], bl[nt][1]);
            }
            #pragma unroll
            for (int mt = 0; mt < 2; mt++)
                #pragma unroll
                for (int nt = 0; nt < 4; nt++) {
                    mma8(acc[mt][nt], ab[mt], bl[nt]);
                    mma8(acc[mt][nt], al[mt], bb[nt]);
                    mma8(acc[mt][nt], ab[mt], bb[nt]);
                }
        }
        __syncthreads();

        if (kc + 2 < 128) loadW(kc + 2, kc & 1);
        cpa_commit();
    }

    // epilogue: add bias, write g_v[bh][t0+row][e]
    #pragma unroll
    for (int mt = 0; mt < 2; mt++) {
        const int row = wm * 32 + mt * 16 + (lane >> 2);
        #pragma unroll
        for (int nt = 0; nt < 4; nt++) {
            const int e0 = wn * 32 + nt * 8 + ((lane & 3) << 1);
            const float b0 = __ldg(&bv[e0]), b1 = __ldg(&bv[e0 + 1]);
            float* o0 = gv + ((size_t)bh * TT + t0 + row) * HS + e0;
            float* o1 = gv + ((size_t)bh * TT + t0 + row + 8) * HS + e0;
            *(float2*)o0 = make_float2(acc[mt][nt][0] + b0, acc[mt][nt][1] + b1);
            *(float2*)o1 = make_float2(acc[mt][nt][2] + b0, acc[mt][nt][3] + b1);
        }
    }
}

// ---------------- cumsum: 2-phase chunked ----------------
__global__ void cumsum_part(float* __restrict__ kcum, float* __restrict__ v,
                            const float* __restrict__ qkv)
{
    const int bh = blockIdx.x, c = blockIdx.y;
    const int b = bh / NHEAD, h = bh % NHEAD;
    const int tid = threadIdx.x;
    const int t0 = c * 256;
    if (tid < HS) {
        const float* src = qkv + (size_t)(b*TT + t0) * QKVROW + CC + h*HS + tid;
        float* dst = kcum + ((size_t)bh*TT + t0) * HS + tid;
        float s = 0.f;
        #pragma unroll 8
        for (int t = 0; t < 256; t++) { s += src[(size_t)t * QKVROW]; dst[t*HS] = s; }
        g_ctot[bh][0][c][tid] = s;
    } else {
        const int d = tid - HS;
        float* p = v + ((size_t)bh*TT + t0) * HS + d;
        float s = 0.f;
        #pragma unroll 8
        for (int t = 0; t < 256; t++) { s += p[t*HS]; p[t*HS] = s; }
        g_ctot[bh][1][c][d] = s;
    }
}

__global__ void cumsum_fix(float* __restrict__ kcum, float* __restrict__ v)
{
    const int bh = blockIdx.x, c = blockIdx.y + 1;   // chunks 1..7
    const int tid = threadIdx.x;
    const int which = tid >> 6, d = tid & 63;
    float pre = 0.f;
    for (int j = 0; j < c; j++) pre += g_ctot[bh][which][j][d];
    float* p = (which ? v : kcum) + ((size_t)bh*TT + c*256) * HS + d;
    #pragma unroll 8
    for (int t = 0; t < 256; t++) p[t*HS] += pre;
}

// ---------------- segment K/V ----------------
__global__ void seg_gather_kernel(float* __restrict__ Kseg, float* __restrict__ Vseg,
                                  const float* __restrict__ kcum, const float* __restrict__ vcum)
{
    const int bh = blockIdx.x;
    const float* kc = kcum + (size_t)bh * TT * HS;
    const float* vc = vcum + (size_t)bh * TT * HS;
    for (int idx = threadIdx.x; idx < NSEG * HS; idx += blockDim.x) {
        int s = idx >> 6, d = idx & 63;
        int l = g_l[s], r = g_r[s];
        float kv = kc[r*HS + d], vv = vc[r*HS + d];
        if (l >= 1) { kv -= kc[(l-1)*HS + d]; vv -= vc[(l-1)*HS + d]; }
        Kseg[(size_t)bh * NSEG * HS + idx] = kv;
        Vseg[(size_t)bh * NSEG * HS + idx] = vv;
    }
}

// ---------------- attention (exact fp32, unchanged) ----------------
__global__ __launch_bounds__(128) void attn_kernel(
    float* __restrict__ out, const float* __restrict__ qkv,
    const float* __restrict__ kcum, const float* __restrict__ vcum,
    const float* __restrict__ Kseg, const float* __restrict__ Vseg)
{
    extern __shared__ float smf[];
    float* Ks = smf;
    float* Vs = smf + NSEG * HS;
    const int bh = blockIdx.x;
    const int b = bh / NHEAD, h = bh % NHEAD;
    const int t = blockIdx.y * 128 + threadIdx.x;

    {
        const float4* Kg = (const float4*)(Kseg + (size_t)bh * NSEG * HS);
        const float4* Vg = (const float4*)(Vseg + (size_t)bh * NSEG * HS);
        float4* Ks4 = (float4*)Ks; float4* Vs4 = (float4*)Vs;
        for (int idx = threadIdx.x; idx < NSEG*HS/4; idx += 128) {
            Ks4[idx] = Kg[idx];
            Vs4[idx] = Vg[idx];
        }
    }
    __syncthreads();

    float4 q4[16];
    const float* qp = qkv + ((size_t)(b*TT + t)) * QKVROW + h * HS;
    #pragma unroll
    for (int j = 0; j < 16; j++) q4[j] = *(const float4*)(qp + j*4);

    float mmax = -INFINITY, lsum = 0.f;
    float4 acc4[16];
    #pragma unroll
    for (int j = 0; j < 16; j++) acc4[j] = make_float4(0.f,0.f,0.f,0.f);

    const float scale = 0.125f;
    int off = 0;
    #pragma unroll 1
    for (int lv = 0; lv < 8; lv++) {
        const int nvalid = (t + 1) >> (4 + lv);
        #pragma unroll 1
        for (int i = 0; i < nvalid; i++) {
            const int s = off + i;
            const float4* kp = (const float4*)(Ks + s*HS);
            float lg = 0.f;
            #pragma unroll
            for (int j = 0; j < 16; j++) {
                float4 kk = kp[j];
                lg = fmaf(kk.x, q4[j].x, lg); lg = fmaf(kk.y, q4[j].y, lg);
                lg = fmaf(kk.z, q4[j].z, lg); lg = fmaf(kk.w, q4[j].w, lg);
            }
            lg *= scale;
            if (lg > mmax) {
                float cc = __expf(mmax - lg);
                lsum *= cc;
                #pragma unroll
                for (int j = 0; j < 16; j++) {
                    acc4[j].x *= cc; acc4[j].y *= cc; acc4[j].z *= cc; acc4[j].w *= cc;
                }
                mmax = lg;
            }
            float p = __expf(lg - mmax);
            lsum += p;
            const float4* vp = (const float4*)(Vs + s*HS);
            #pragma unroll
            for (int j = 0; j < 16; j++) {
                float4 vv = vp[j];
                acc4[j].x = fmaf(p, vv.x, acc4[j].x);
                acc4[j].y = fmaf(p, vv.y, acc4[j].y);
                acc4[j].z = fmaf(p, vv.z, acc4[j].z);
                acc4[j].w = fmaf(p, vv.w, acc4[j].w);
            }
        }
        off += 128 >> lv;
    }

    const int lt = t & ~15;
    const float4* kc4 = (const float4*)(kcum + (size_t)bh * TT * HS);
    const float4* vc4 = (const float4*)(vcum + (size_t)bh * TT * HS);
    float lg = 0.f;
    #pragma unroll
    for (int j = 0; j < 16; j++) {
        float4 kt = kc4[t*16 + j];
        if (lt >= 1) {
            float4 kl = kc4[(lt-1)*16 + j];
            kt.x -= kl.x; kt.y -= kl.y; kt.z -= kl.z; kt.w -= kl.w;
        }
        lg = fmaf(kt.x, q4[j].x, lg); lg = fmaf(kt.y, q4[j].y, lg);
        lg = fmaf(kt.z, q4[j].z, lg); lg = fmaf(kt.w, q4[j].w, lg);
    }
    lg *= scale;
    if (lg > mmax) {
        float cc = __expf(mmax - lg);
        lsum *= cc;
        #pragma unroll
        for (int j = 0; j < 16; j++) {
            acc4[j].x *= cc; acc4[j].y *= cc; acc4[j].z *= cc; acc4[j].w *= cc;
        }
        mmax = lg;
    }
    {
        float p = __expf(lg - mmax);
        lsum += p;
        #pragma unroll
        for (int j = 0; j < 16; j++) {
            float4 vt = vc4[t*16 + j];
            if (lt >= 1) {
                float4 vl = vc4[(lt-1)*16 + j];
                vt.x -= vl.x; vt.y -= vl.y; vt.z -= vl.z; vt.w -= vl.w;
            }
            acc4[j].x = fmaf(p, vt.x, acc4[j].x);
            acc4[j].y = fmaf(p, vt.y, acc4[j].y);
            acc4[j].z = fmaf(p, vt.z, acc4[j].z);
            acc4[j].w = fmaf(p, vt.w, acc4[j].w);
        }
    }

    const float inv = 1.0f / lsum;
    float* op = out + ((size_t)(b*TT + t)) * CC + h * HS;
    #pragma unroll
    for (int j = 0; j < 16; j++) {
        *(float4*)(op + j*4) = make_float4(acc4[j].x*inv, acc4[j].y*inv,
                                           acc4[j].z*inv, acc4[j].w*inv);
    }
}

// ---------------- launch ----------------
extern "C" void kernel_launch(void* const* d_in, const int* in_sizes, int n_in,
                              void* d_out, int out_size)
{
    const float* x     = (const float*)d_in[0];
    const float* Wqkv  = (const float*)d_in[1];
    const float* Wproj = (const float*)d_in[2];
    const float* Wv    = (const float*)d_in[3];
    const float* bv    = (const float*)d_in[4];
    float* out = (float*)d_out;

    float *qkv, *v, *kcum, *Kseg, *Vseg, *att;
    cudaGetSymbolAddress((void**)&qkv,  g_qkv);
    cudaGetSymbolAddress((void**)&v,    g_v);
    cudaGetSymbolAddress((void**)&kcum, g_kcum);
    cudaGetSymbolAddress((void**)&Kseg, g_Kseg);
    cudaGetSymbolAddress((void**)&Vseg, g_Vseg);
    cudaGetSymbolAddress((void**)&att,  g_att);

    const int gemm_smem = 3 * GSTAGEF * 4;                               // 110592
    cudaFuncSetAttribute(mma_gemm_tn, cudaFuncAttributeMaxDynamicSharedMemorySize, gemm_smem);
    const int v_smem = (128*64 + 128*VPAD + 2*64*VPAD) * 4;              // 69632
    cudaFuncSetAttribute(v_mma_kernel, cudaFuncAttributeMaxDynamicSharedMemorySize, v_smem);
    const int attn_smem = 2 * NSEG * HS * (int)sizeof(float);            // 130560
    cudaFuncSetAttribute(attn_kernel, cudaFuncAttributeMaxDynamicSharedMemorySize, attn_smem);

    seg_init_kernel<<<1, 256>>>();

    // qkv = x @ Wqkv^T : M=16384, N=2304, K=768
    mma_gemm_tn<<<dim3(QKVROW/128, (BB*TT)/128), 256, gemm_smem>>>(qkv, x, Wqkv, QKVROW, CC);

    // v bilinear via fused Z-GEMM
    v_mma_kernel<<<BH*TT/128, 256, v_smem>>>(v, qkv, Wv, bv);

    // cumsums, 2-phase
    cumsum_part<<<dim3(BH, 8), 128>>>(kcum, v, qkv);
    cumsum_fix<<<dim3(BH, 7), 128>>>(kcum, v);

    // segment K/V
    seg_gather_kernel<<<BH, 256>>>(Kseg, Vseg, kcum, v);

    // attention
    attn_kernel<<<dim3(BH, TT/128), 128, attn_smem>>>(att, qkv, kcum, v, Kseg, Vseg);

    // out = att @ Wproj^T : M=16384, N=768, K=768
    mma_gemm_tn<<<dim3(CC/128, (BB*TT)/128), 256, gemm_smem>>>(out, att, Wproj, CC, CC);
}